// round 7
// baseline (speedup 1.0000x reference)
#include <cuda_runtime.h>
#include <math.h>

#define Nn 1024
#define Ff 64
#define ALPHA 0.2f

// scratch
__device__ __align__(16) float g_Wh[Nn * Ff];
__device__ float g_e1[Nn];
__device__ float g_e2[Nn];
__device__ unsigned int g_bar;                 // epoch barrier counter (monotonic)
__device__ unsigned int g_pair[256];           // per-rowgroup pair tickets (monotonic)
__device__ __align__(16) float g_po[256][2][260];  // partial out[256] + dsum[4] per (rg, js)

// ---------------------------------------------------------------------------
// Fully fused GAT layer, one launch, grid 512 x 256.
// Block b: phase1 computes Wh rows {2b, 2b+1} (+ e1,e2); global epoch
// barrier; phase2 computes the (rg=b>>1, js=b&1) partial of the attention
// GEMM over j in [js*512, js*512+512) for rows rg*4..rg*4+3 (unnormalized
// softmax weights); phase3 pairwise-combines the two j-halves via a
// per-rowgroup atomic ticket: second arriver normalizes + elu + stores out.
// __launch_bounds__(256,4) caps regs at 62 -> >=4 CTA/SM -> all 512 CTAs
// co-resident (smem 34KB*4 = 136KB <= 228KB) -> barrier cannot deadlock.
// ---------------------------------------------------------------------------
__global__ __launch_bounds__(256, 4) void gat_fused(
        const float* __restrict__ h, const int* __restrict__ adj,
        const float* __restrict__ W, const float* __restrict__ a,
        float* __restrict__ out) {
    __shared__ __align__(16) float ps[512 * 8];   // 16KB p dup-pairs; = W stage in phase1
    __shared__ __align__(16) float red[16 * 264]; // 16.5KB split-reduction buffer
    __shared__ float hs[2 * 64];
    __shared__ float a1s[64], a2s[64];
    __shared__ float es1[4], es2[4];
    __shared__ float wpart[8][4];
    __shared__ unsigned int s_second;

    int t = threadIdx.x;
    int b = blockIdx.x;
    int rg = b >> 1;
    int js = b & 1;
    int r0 = rg * 4;
    int jb = js * 512;

    // ---- prefetch our adj tile into L2 (hidden behind phase1+barrier) ----
    {
        const int* base = adj + jb + t;
#pragma unroll
        for (int ii = 0; ii < 4; ii++) {
            asm volatile("prefetch.global.L2 [%0];" :: "l"(base + (size_t)(r0 + ii) * Nn));
            asm volatile("prefetch.global.L2 [%0];" :: "l"(base + (size_t)(r0 + ii) * Nn + 256));
        }
    }

    // ---- phase 1: Wh rows 2b, 2b+1 ; e1,e2 for those rows ----
    {
        float* Ws = ps;                       // 4096 floats, overlays ps
#pragma unroll
        for (int k = 0; k < 4; k++)
            ((float4*)Ws)[t + k * 256] = ((const float4*)W)[t + k * 256];
        int p1r = b * 2;
        if (t < 128) hs[t] = h[p1r * Ff + t];
        if (t < 64) { a1s[t] = a[t]; a2s[t] = a[64 + t]; }
        __syncthreads();
        if (t < 128) {
            int ii = t >> 6, f = t & 63;
            float acc = 0.f;
#pragma unroll
            for (int k = 0; k < 64; k++)
                acc += hs[ii * 64 + k] * Ws[k * 64 + f];
            g_Wh[(p1r + ii) * Ff + f] = acc;
            float p1 = acc * a1s[f], p2 = acc * a2s[f];
#pragma unroll
            for (int o = 16; o; o >>= 1) {
                p1 += __shfl_xor_sync(0xffffffffu, p1, o);
                p2 += __shfl_xor_sync(0xffffffffu, p2, o);
            }
            int w = t >> 5;
            if ((t & 31) == 0) { es1[w] = p1; es2[w] = p2; }
        }
        __syncthreads();
        if (t < 2) {
            g_e1[b * 2 + t] = es1[2 * t] + es1[2 * t + 1];
            g_e2[b * 2 + t] = es2[2 * t] + es2[2 * t + 1];
        }
    }

    // ---- global epoch barrier ----
    __threadfence();
    __syncthreads();
    if (t == 0) {
        unsigned int old = atomicAdd(&g_bar, 1u);
        unsigned int target = (old & ~511u) + 512u;
        while (*(volatile unsigned int*)&g_bar < target) { }
        __threadfence();
    }
    __syncthreads();

    // ---- phase 2: p tile (unnormalized softmax weights) + dsum ----
    float e1r0 = __ldg(&g_e1[r0 + 0]);
    float e1r1 = __ldg(&g_e1[r0 + 1]);
    float e1r2 = __ldg(&g_e1[r0 + 2]);
    float e1r3 = __ldg(&g_e1[r0 + 3]);
    float d0 = 0.f, d1 = 0.f, d2 = 0.f, d3 = 0.f;
#pragma unroll
    for (int jt = 0; jt < 2; jt++) {
        int j = jt * 256 + t;
        float e2 = __ldg(&g_e2[jb + j]);
        const int* ac = adj + jb + j;
        int a0 = __ldg(ac + (size_t)(r0 + 0) * Nn);
        int a1v = __ldg(ac + (size_t)(r0 + 1) * Nn);
        int a2v = __ldg(ac + (size_t)(r0 + 2) * Nn);
        int a3v = __ldg(ac + (size_t)(r0 + 3) * Nn);
        float s0 = e1r0 + e2; s0 = (s0 > 0.f) ? s0 : ALPHA * s0;
        float s1 = e1r1 + e2; s1 = (s1 > 0.f) ? s1 : ALPHA * s1;
        float s2 = e1r2 + e2; s2 = (s2 > 0.f) ? s2 : ALPHA * s2;
        float s3 = e1r3 + e2; s3 = (s3 > 0.f) ? s3 : ALPHA * s3;
        float p0 = (a0 > 0)  ? __expf(s0) : 0.f;
        float p1 = (a1v > 0) ? __expf(s1) : 0.f;
        float p2 = (a2v > 0) ? __expf(s2) : 0.f;
        float p3 = (a3v > 0) ? __expf(s3) : 0.f;
        d0 += p0; d1 += p1; d2 += p2; d3 += p3;
        float* bp = &ps[j * 8];
        *(float4*)(bp)     = make_float4(p0, p0, p1, p1);
        *(float4*)(bp + 4) = make_float4(p2, p2, p3, p3);
    }
    __syncthreads();

    // ---- GEMM over 512 j: thread (fi, jg), 32 j-steps ----
    int fi = t & 15;
    int jg = t >> 4;
    const ulonglong2* WhL = (const ulonglong2*)g_Wh;
    unsigned long long acc_lo[4] = {0ull, 0ull, 0ull, 0ull};
    unsigned long long acc_hi[4] = {0ull, 0ull, 0ull, 0ull};

#pragma unroll 8
    for (int k = 0; k < 32; k++) {
        int j = k * 16 + jg;
        ulonglong2 wh = WhL[(size_t)(jb + j) * 16 + fi];
        ulonglong2 pA = *(const ulonglong2*)&ps[j * 8];
        ulonglong2 pB = *(const ulonglong2*)&ps[j * 8 + 4];
        asm("fma.rn.f32x2 %0,%1,%2,%0;" : "+l"(acc_lo[0]) : "l"(pA.x), "l"(wh.x));
        asm("fma.rn.f32x2 %0,%1,%2,%0;" : "+l"(acc_hi[0]) : "l"(pA.x), "l"(wh.y));
        asm("fma.rn.f32x2 %0,%1,%2,%0;" : "+l"(acc_lo[1]) : "l"(pA.y), "l"(wh.x));
        asm("fma.rn.f32x2 %0,%1,%2,%0;" : "+l"(acc_hi[1]) : "l"(pA.y), "l"(wh.y));
        asm("fma.rn.f32x2 %0,%1,%2,%0;" : "+l"(acc_lo[2]) : "l"(pB.x), "l"(wh.x));
        asm("fma.rn.f32x2 %0,%1,%2,%0;" : "+l"(acc_hi[2]) : "l"(pB.x), "l"(wh.y));
        asm("fma.rn.f32x2 %0,%1,%2,%0;" : "+l"(acc_lo[3]) : "l"(pB.y), "l"(wh.x));
        asm("fma.rn.f32x2 %0,%1,%2,%0;" : "+l"(acc_hi[3]) : "l"(pB.y), "l"(wh.y));
    }

    // ---- dsum reduction to wpart ----
#pragma unroll
    for (int o = 16; o; o >>= 1) {
        d0 += __shfl_xor_sync(0xffffffffu, d0, o);
        d1 += __shfl_xor_sync(0xffffffffu, d1, o);
        d2 += __shfl_xor_sync(0xffffffffu, d2, o);
        d3 += __shfl_xor_sync(0xffffffffu, d3, o);
    }
    if ((t & 31) == 0) {
        int w = t >> 5;
        wpart[w][0] = d0; wpart[w][1] = d1; wpart[w][2] = d2; wpart[w][3] = d3;
    }

    // ---- write register tiles to red ----
#pragma unroll
    for (int ii = 0; ii < 4; ii++) {
        float2 lo = *(float2*)&acc_lo[ii];
        float2 hi = *(float2*)&acc_hi[ii];
        *(float4*)&red[jg * 264 + ii * 64 + fi * 4] = make_float4(lo.x, lo.y, hi.x, hi.y);
    }
    __syncthreads();

    // ---- per-thread final partial: output element t of the 4x64 tile ----
    int oii = t >> 6;
    int of  = t & 63;
    float val = 0.f;
#pragma unroll
    for (int g = 0; g < 16; g++) val += red[g * 264 + t];
    float dblk = 0.f;
#pragma unroll
    for (int w2 = 0; w2 < 8; w2++) dblk += wpart[w2][oii];

    // ---- phase 3: pairwise combine across the two j-halves ----
    g_po[rg][js][t] = val;
    if (t < 4) {
        float dd = 0.f;
#pragma unroll
        for (int w2 = 0; w2 < 8; w2++) dd += wpart[w2][t];
        g_po[rg][js][256 + t] = dd;
    }
    __threadfence();
    __syncthreads();
    if (t == 0) {
        unsigned int c = atomicAdd(&g_pair[rg], 1u);
        s_second = (c & 1u);
        __threadfence();
    }
    __syncthreads();
    if (s_second) {
        float oval = *(volatile float*)&g_po[rg][1 - js][t];
        float od   = *(volatile float*)&g_po[rg][1 - js][256 + oii];
        float tot = val + oval;
        float dd  = dblk + od;
        float r = tot / dd;
        r = (r > 0.f) ? r : expm1f(r);
        out[(size_t)(r0 + oii) * Ff + of] = r;
    }
}

// ---------------------------------------------------------------------------
extern "C" void kernel_launch(void* const* d_in, const int* in_sizes, int n_in,
                              void* d_out, int out_size) {
    const float* h   = (const float*)d_in[0];
    const int*   adj = (const int*)d_in[1];
    const float* W   = (const float*)d_in[2];
    const float* a   = (const float*)d_in[3];
    float* out = (float*)d_out;

    gat_fused<<<512, 256>>>(h, adj, W, a, out);
}

// round 8
// speedup vs baseline: 1.0189x; 1.0189x over previous
#include <cuda_runtime.h>
#include <math.h>

#define Nn 1024
#define Ff 64
#define ALPHA 0.2f

// scratch
__device__ __align__(16) float g_Wh[Nn * Ff];
__device__ float g_e1[Nn];
__device__ float g_e2[Nn];
__device__ unsigned int g_pair[256];              // per-rowgroup tickets (monotonic)
__device__ __align__(16) float g_po[256][2][260]; // partial out[256] + dsum[4] per (rg, js)

// ---------------------------------------------------------------------------
// k1: Wh = h @ W ; e1 = Wh@a1 ; e2 = Wh@a2. grid 256 (4 rows/block),
// SMEM-staged W, 1 output/thread.
// ---------------------------------------------------------------------------
__global__ __launch_bounds__(256) void gat_k1(const float* __restrict__ h,
                                              const float* __restrict__ W,
                                              const float* __restrict__ a) {
    __shared__ float Ws[Ff * Ff];
    __shared__ float hs[4 * Ff];
    __shared__ float a1s[Ff], a2s[Ff];
    __shared__ float es1[8], es2[8];
    int t = threadIdx.x;
    int row0 = blockIdx.x * 4;

#pragma unroll
    for (int k = 0; k < 4; k++)
        ((float4*)Ws)[t + k * 256] = ((const float4*)W)[t + k * 256];
    hs[t] = h[row0 * Ff + t];
    if (t < Ff) { a1s[t] = a[t]; a2s[t] = a[Ff + t]; }
    __syncthreads();

    int ii = t >> 6;
    int f  = t & 63;
    float acc = 0.f;
#pragma unroll
    for (int k = 0; k < Ff; k++)
        acc += hs[ii * Ff + k] * Ws[k * Ff + f];
    int row = row0 + ii;
    g_Wh[row * Ff + f] = acc;

    float p1 = acc * a1s[f];
    float p2 = acc * a2s[f];
#pragma unroll
    for (int o = 16; o; o >>= 1) {
        p1 += __shfl_xor_sync(0xffffffffu, p1, o);
        p2 += __shfl_xor_sync(0xffffffffu, p2, o);
    }
    int w = t >> 5;
    if ((t & 31) == 0) { es1[w] = p1; es2[w] = p2; }
    __syncthreads();
    if (t < 4) {
        g_e1[row0 + t] = es1[2 * t] + es1[2 * t + 1];
        g_e2[row0 + t] = es2[2 * t] + es2[2 * t + 1];
    }
}

// ---------------------------------------------------------------------------
// k2: attention GEMM, grid 512 = 256 rowgroups x 2 j-halves, 256 threads.
// Block (rg, js): rows rg*4..+4, j in [js*512, +512).
// Unnormalized softmax weights; p dup-pairs in SMEM (stride 8);
// 32-step GEMM with ulonglong2 Wh loads; pairwise finalize via per-rg
// atomic ticket: second arriver sums both halves' partials (commutative ->
// deterministic), normalizes, elu, stores.
// ---------------------------------------------------------------------------
__global__ __launch_bounds__(256, 4) void gat_k2(const int* __restrict__ adj,
                                                 float* __restrict__ out) {
    __shared__ __align__(16) float ps[512 * 8];   // 16KB p dup-pairs
    __shared__ __align__(16) float red[16 * 264]; // 16.5KB reduction buffer
    __shared__ float wpart[8][4];
    __shared__ unsigned int s_second;

    int t = threadIdx.x;
    int b = blockIdx.x;
    int rg = b >> 1;
    int js = b & 1;
    int r0 = rg * 4;
    int jb = js * 512;

    // ---- hoisted loads: adj[2 tiles][4 rows], e2[2 tiles], e1[4] ----
    int av[2][4];
    float e2v[2];
#pragma unroll
    for (int jt = 0; jt < 2; jt++) {
        const int* ac = adj + jb + jt * 256 + t;
#pragma unroll
        for (int ii = 0; ii < 4; ii++)
            av[jt][ii] = __ldg(ac + (size_t)(r0 + ii) * Nn);
        e2v[jt] = __ldg(&g_e2[jb + jt * 256 + t]);
    }
    float e1r0 = __ldg(&g_e1[r0 + 0]);
    float e1r1 = __ldg(&g_e1[r0 + 1]);
    float e1r2 = __ldg(&g_e1[r0 + 2]);
    float e1r3 = __ldg(&g_e1[r0 + 3]);

    // ---- p tile + dsum ----
    float d0 = 0.f, d1 = 0.f, d2 = 0.f, d3 = 0.f;
#pragma unroll
    for (int jt = 0; jt < 2; jt++) {
        int j = jt * 256 + t;
        float e2 = e2v[jt];
        float s0 = e1r0 + e2; s0 = (s0 > 0.f) ? s0 : ALPHA * s0;
        float s1 = e1r1 + e2; s1 = (s1 > 0.f) ? s1 : ALPHA * s1;
        float s2 = e1r2 + e2; s2 = (s2 > 0.f) ? s2 : ALPHA * s2;
        float s3 = e1r3 + e2; s3 = (s3 > 0.f) ? s3 : ALPHA * s3;
        float p0 = (av[jt][0] > 0) ? __expf(s0) : 0.f;
        float p1 = (av[jt][1] > 0) ? __expf(s1) : 0.f;
        float p2 = (av[jt][2] > 0) ? __expf(s2) : 0.f;
        float p3 = (av[jt][3] > 0) ? __expf(s3) : 0.f;
        d0 += p0; d1 += p1; d2 += p2; d3 += p3;
        float* bp = &ps[j * 8];
        *(float4*)(bp)     = make_float4(p0, p0, p1, p1);
        *(float4*)(bp + 4) = make_float4(p2, p2, p3, p3);
    }
    __syncthreads();

    // ---- GEMM over 512 j: thread (fi, jg), 32 j-steps ----
    int fi = t & 15;
    int jg = t >> 4;
    const ulonglong2* WhL = (const ulonglong2*)g_Wh;
    unsigned long long acc_lo[4] = {0ull, 0ull, 0ull, 0ull};
    unsigned long long acc_hi[4] = {0ull, 0ull, 0ull, 0ull};

#pragma unroll 8
    for (int k = 0; k < 32; k++) {
        int j = k * 16 + jg;
        ulonglong2 wh = WhL[(size_t)(jb + j) * 16 + fi];
        ulonglong2 pA = *(const ulonglong2*)&ps[j * 8];
        ulonglong2 pB = *(const ulonglong2*)&ps[j * 8 + 4];
        asm("fma.rn.f32x2 %0,%1,%2,%0;" : "+l"(acc_lo[0]) : "l"(pA.x), "l"(wh.x));
        asm("fma.rn.f32x2 %0,%1,%2,%0;" : "+l"(acc_hi[0]) : "l"(pA.x), "l"(wh.y));
        asm("fma.rn.f32x2 %0,%1,%2,%0;" : "+l"(acc_lo[1]) : "l"(pA.y), "l"(wh.x));
        asm("fma.rn.f32x2 %0,%1,%2,%0;" : "+l"(acc_hi[1]) : "l"(pA.y), "l"(wh.y));
        asm("fma.rn.f32x2 %0,%1,%2,%0;" : "+l"(acc_lo[2]) : "l"(pB.x), "l"(wh.x));
        asm("fma.rn.f32x2 %0,%1,%2,%0;" : "+l"(acc_hi[2]) : "l"(pB.x), "l"(wh.y));
        asm("fma.rn.f32x2 %0,%1,%2,%0;" : "+l"(acc_lo[3]) : "l"(pB.y), "l"(wh.x));
        asm("fma.rn.f32x2 %0,%1,%2,%0;" : "+l"(acc_hi[3]) : "l"(pB.y), "l"(wh.y));
    }

    // ---- dsum reduction ----
#pragma unroll
    for (int o = 16; o; o >>= 1) {
        d0 += __shfl_xor_sync(0xffffffffu, d0, o);
        d1 += __shfl_xor_sync(0xffffffffu, d1, o);
        d2 += __shfl_xor_sync(0xffffffffu, d2, o);
        d3 += __shfl_xor_sync(0xffffffffu, d3, o);
    }
    if ((t & 31) == 0) {
        int w = t >> 5;
        wpart[w][0] = d0; wpart[w][1] = d1; wpart[w][2] = d2; wpart[w][3] = d3;
    }

    // ---- write register tiles to red ----
#pragma unroll
    for (int ii = 0; ii < 4; ii++) {
        float2 lo = *(float2*)&acc_lo[ii];
        float2 hi = *(float2*)&acc_hi[ii];
        *(float4*)&red[jg * 264 + ii * 64 + fi * 4] = make_float4(lo.x, lo.y, hi.x, hi.y);
    }
    __syncthreads();

    // ---- per-thread partial for output element t of the 4x64 tile ----
    int oii = t >> 6;
    int of  = t & 63;
    float val = 0.f;
#pragma unroll
    for (int g = 0; g < 16; g++) val += red[g * 264 + t];
    float dblk = 0.f;
#pragma unroll
    for (int w2 = 0; w2 < 8; w2++) dblk += wpart[w2][oii];

    // ---- pairwise combine across the two j-halves ----
    g_po[rg][js][t] = val;
    if (t < 4) {
        float dd = 0.f;
#pragma unroll
        for (int w2 = 0; w2 < 8; w2++) dd += wpart[w2][t];
        g_po[rg][js][256 + t] = dd;
    }
    __threadfence();
    __syncthreads();
    if (t == 0) {
        unsigned int c = atomicAdd(&g_pair[rg], 1u);
        s_second = (c & 1u);
        __threadfence();
    }
    __syncthreads();
    if (s_second) {
        float oval = *(volatile float*)&g_po[rg][1 - js][t];
        float od   = *(volatile float*)&g_po[rg][1 - js][256 + oii];
        float tot = val + oval;
        float dd  = dblk + od;
        float r = tot / dd;
        r = (r > 0.f) ? r : expm1f(r);
        out[(size_t)(r0 + oii) * Ff + of] = r;
    }
}

// ---------------------------------------------------------------------------
extern "C" void kernel_launch(void* const* d_in, const int* in_sizes, int n_in,
                              void* d_out, int out_size) {
    const float* h   = (const float*)d_in[0];
    const int*   adj = (const int*)d_in[1];
    const float* W   = (const float*)d_in[2];
    const float* a   = (const float*)d_in[3];
    float* out = (float*)d_out;

    gat_k1<<<256, 256>>>(h, W, a);
    gat_k2<<<512, 256>>>(adj, out);
}